// round 17
// baseline (speedup 1.0000x reference)
#include <cuda_runtime.h>
#include <cuda_bf16.h>
#include <cuda_fp16.h>
#include <math.h>
#include <stdint.h>

#define NB 4
#define NH 16
#define TT 2048
#define DH 64
#define CC 1024
#define MROWS (NB*TT)   // 8192
#define KDIM  1024

// ---------------------------------------------------------------------------
// Scratch (__device__ globals; allocation-free rule)
// ---------------------------------------------------------------------------
// q, k, v: single fp16 planes [B,H,T,D]
__device__ __half g_qf[NB*NH*TT*DH];
__device__ __half g_kf[NB*NH*TT*DH];
__device__ __half g_vf[NB*NH*TT*DH];

// y (attention out) single fp16 plane [B,T,C], written by flash epilogue
__device__ __half g_yf[(size_t)MROWS*KDIM];

// GEMM inputs: single fp16 planes
__device__ __half g_xf[(size_t)MROWS*KDIM];      // x
__device__ __half g_wqf[(size_t)3072*KDIM];      // Wqkv^T [3072][K]
__device__ __half g_wpf[(size_t)1024*KDIM];      // Wproj^T [1024][K]

// ---------------------------------------------------------------------------
// PTX helpers — compute_80-era ops only (harness PTX target lacks 'a' features)
// ---------------------------------------------------------------------------
__device__ __forceinline__ uint32_t smem_to_u32(const void* p) {
    uint32_t a;
    asm("{ .reg .u64 t; cvta.to.shared.u64 t, %1; cvt.u32.u64 %0, t; }"
        : "=r"(a) : "l"(p));
    return a;
}
__device__ __forceinline__ void cp16(uint32_t saddr, const void* g) {
    asm volatile("cp.async.cg.shared.global [%0], [%1], 16;"
                 :: "r"(saddr), "l"(g) : "memory");
}
__device__ __forceinline__ void ldm_x4(uint32_t (&r)[4], uint32_t addr) {
    asm volatile("ldmatrix.sync.aligned.m8n8.x4.shared.b16 {%0,%1,%2,%3}, [%4];"
        : "=r"(r[0]), "=r"(r[1]), "=r"(r[2]), "=r"(r[3]) : "r"(addr));
}
__device__ __forceinline__ void ldm_x4_t(uint32_t (&r)[4], uint32_t addr) {
    asm volatile("ldmatrix.sync.aligned.m8n8.x4.trans.shared.b16 {%0,%1,%2,%3}, [%4];"
        : "=r"(r[0]), "=r"(r[1]), "=r"(r[2]), "=r"(r[3]) : "r"(addr));
}
__device__ __forceinline__ void mma_f16(float (&d)[4], const uint32_t (&a)[4],
                                        uint32_t b0, uint32_t b1) {
    asm volatile("mma.sync.aligned.m16n8k16.row.col.f32.f16.f16.f32 "
        "{%0,%1,%2,%3}, {%4,%5,%6,%7}, {%8,%9}, {%0,%1,%2,%3};"
        : "+f"(d[0]), "+f"(d[1]), "+f"(d[2]), "+f"(d[3])
        : "r"(a[0]), "r"(a[1]), "r"(a[2]), "r"(a[3]), "r"(b0), "r"(b1));
}
// pack two fp32 into f16x2 word: low half = lo_elem
__device__ __forceinline__ uint32_t pack_hf(float lo_elem, float hi_elem) {
    __half2 h = __floats2half2_rn(lo_elem, hi_elem);
    return *(uint32_t*)&h;
}

// ---------------------------------------------------------------------------
// Conversion kernels
// ---------------------------------------------------------------------------
// x -> g_xf (single fp16 plane)
__global__ __launch_bounds__(256) void conv_x(const float* __restrict__ in)
{
    const size_t i = (size_t)blockIdx.x * 256 + threadIdx.x;   // per float4
    float4 v = ((const float4*)in)[i];
    __half h[4];
    h[0] = __float2half_rn(v.x); h[1] = __float2half_rn(v.y);
    h[2] = __float2half_rn(v.z); h[3] = __float2half_rn(v.w);
    *(uint2*)(g_xf + 4*i) = *(uint2*)h;
}

// W [K][N] -> out [N][K] (single fp16 plane, transposed)
template<int N>
__global__ __launch_bounds__(256) void conv_w(const float* __restrict__ W)
{
    __half* out = (N == 3072) ? g_wqf : g_wpf;
    __shared__ float t[32][33];
    const int k0 = blockIdx.x * 32, n0 = blockIdx.y * 32;
    const int tx = threadIdx.x, ty = threadIdx.y;      // 32 x 8
    #pragma unroll
    for (int i = 0; i < 4; i++)
        t[ty + 8*i][tx] = W[(size_t)(k0 + ty + 8*i) * N + n0 + tx];
    __syncthreads();
    #pragma unroll
    for (int i = 0; i < 4; i++)
        out[(size_t)(n0 + ty + 8*i) * KDIM + k0 + tx] =
            __float2half_rn(t[tx][ty + 8*i]);
}

#define PLANE_BYTES 10240          // 128 rows * 80 B (32 elems*2B + 16B pad)
#define GEMM_STAGE (2*PLANE_BYTES) // 20480
#define GEMM_SMEM  (4*GEMM_STAGE)  // 81920 (4-stage ring)

// ---------------------------------------------------------------------------
// Single-term fp16 GEMM core (frozen from R16-passing config).
// 256 threads, 8 warps, warp tile 32x64, 4-stage cp.async ring, BK=32.
// MODE 0: A=g_xf, B=g_wqf (N=3072) -> q,k,v fp16 [B,H,T,D]
// MODE 1: A=g_yf, B=g_wpf (N=1024) -> Out fp32 [B,T,C]
// ---------------------------------------------------------------------------
template<int MODE>
__global__ __launch_bounds__(256, 2)
void gemm_f16_kernel(const float* __restrict__ bias, float* __restrict__ Out)
{
    extern __shared__ __align__(128) char smem[];
    const __half* __restrict__ Ap = MODE ? g_yf : g_xf;
    const __half* __restrict__ Bp = MODE ? g_wpf : g_wqf;

    const int tid  = threadIdx.x;
    const int lane = tid & 31, wid = tid >> 5;
    const int row0 = blockIdx.y * 128, col0 = blockIdx.x * 128;
    const int m0w  = (wid >> 1) * 32;
    const int n0w  = (wid & 1) * 64;
    const uint32_t sb = smem_to_u32(smem);

    float acc[2][8][4];
    #pragma unroll
    for (int a = 0; a < 2; a++)
        #pragma unroll
        for (int b = 0; b < 8; b++)
            #pragma unroll
            for (int c = 0; c < 4; c++) acc[a][b][c] = 0.f;

    auto issue = [&](int ck) {
        const int k0 = ck * 32;
        const uint32_t s0 = sb + (ck & 3) * GEMM_STAGE;
        #pragma unroll
        for (int i = 0; i < 2; i++) {
            const int c = tid + i * 256;       // 512 16B chunks per plane
            const int r = c >> 2, kc = c & 3;
            const uint32_t so = r * 80 + kc * 16;
            cp16(s0 + so, Ap + (size_t)(row0 + r) * KDIM + k0 + kc * 8);
            cp16(s0 + PLANE_BYTES + so,
                 Bp + (size_t)(col0 + r) * KDIM + k0 + kc * 8);
        }
        asm volatile("cp.async.commit_group;" ::: "memory");
    };

    auto compute = [&](int st) {
        const uint32_t s0 = sb + st * GEMM_STAGE;
        const uint32_t rsel = (lane & 15);
        #pragma unroll
        for (int ks = 0; ks < 32; ks += 16) {
            const uint32_t coff = ks * 2 + 16 * (lane >> 4);
            uint32_t af[2][4];
            #pragma unroll
            for (int mt = 0; mt < 2; mt++)
                ldm_x4(af[mt], s0 + (m0w + mt*16 + rsel) * 80 + coff);
            #pragma unroll
            for (int nt = 0; nt < 4; nt++) {
                uint32_t bh[4];
                ldm_x4(bh, s0 + PLANE_BYTES + (n0w + nt*16 + rsel) * 80 + coff);
                #pragma unroll
                for (int mt = 0; mt < 2; mt++) {
                    mma_f16(acc[mt][nt*2],   af[mt], bh[0], bh[2]);
                    mma_f16(acc[mt][nt*2+1], af[mt], bh[1], bh[3]);
                }
            }
        }
    };

    issue(0); issue(1); issue(2);
    for (int ck = 0; ck < 32; ck++) {
        if (ck < 30)      { asm volatile("cp.async.wait_group 2;" ::: "memory"); }
        else if (ck == 30){ asm volatile("cp.async.wait_group 1;" ::: "memory"); }
        else              { asm volatile("cp.async.wait_group 0;" ::: "memory"); }
        __syncthreads();   // all warps done with stage (ck-1)&3 -> safe to refill
        if (ck + 3 < 32) issue(ck + 3);
        compute(ck & 3);
    }

    // ---- epilogue ----
    const int g   = lane >> 2;
    const int cql = (lane & 3) * 2;
    #pragma unroll
    for (int mt = 0; mt < 2; mt++) {
        #pragma unroll
        for (int nt = 0; nt < 8; nt++) {
            const int cg = col0 + n0w + nt * 8 + cql;
            const float b0 = bias[cg], b1 = bias[cg + 1];
            const int r0 = row0 + m0w + mt * 16 + g;
            if (MODE == 0) {
                const int which = cg >> 10;
                const int rem = cg & (CC - 1);
                const int h = rem >> 6, d0 = rem & (DH - 1);
                uint32_t* dst = (which == 0) ? (uint32_t*)g_qf
                              : (which == 1) ? (uint32_t*)g_kf
                                             : (uint32_t*)g_vf;
                #pragma unroll
                for (int hf = 0; hf < 2; hf++) {
                    const float vx = acc[mt][nt][hf*2]   + b0;
                    const float vy = acc[mt][nt][hf*2+1] + b1;
                    const int rr = r0 + hf * 8;
                    const int bb = rr >> 11, t = rr & (TT - 1);
                    const size_t off = (((size_t)(bb*NH + h)*TT + t)*DH + d0) >> 1;
                    dst[off] = pack_hf(vx, vy);
                }
            } else {
                *(float2*)(Out + (size_t)r0 * CC + cg) =
                    make_float2(acc[mt][nt][0] + b0, acc[mt][nt][1] + b1);
                *(float2*)(Out + (size_t)(r0 + 8) * CC + cg) =
                    make_float2(acc[mt][nt][2] + b0, acc[mt][nt][3] + b1);
            }
        }
    }
}

// ---------------------------------------------------------------------------
// Flash attention, single fp16 planes. Br=128 (8 warps x m16), Bc=64.
// 3-stage cp.async ring, ONE sync per KV tile.
// NEW: exp2-domain softmax (scale folds log2e; exp2f = bare MUFU) and
// warp-uniform skip of fully-masked n8/k16 sub-tiles in diagonal tiles.
// Epilogue writes y directly as fp16 (g_yf) for the fp16 proj GEMM.
// ---------------------------------------------------------------------------
#define QPL  9216                    // 64 * 144   (KV plane)
#define QPL2 18432                   // 128 * 144  (Q plane)
#define FL_STAGE (2*QPL)             // K, V
#define FL_SMEM_BYTES (QPL2 + 3*FL_STAGE)   // 73728 (3-stage ring)
#define SM_SCALE2 0.18033688011112042f      // 0.125 * log2(e)

__global__ __launch_bounds__(256)
void flash_mma_kernel()
{
    extern __shared__ __align__(128) char smem[];
    const uint32_t sb = smem_to_u32(smem);
    const int tid = threadIdx.x, lane = tid & 31, wid = tid >> 5;
    const int qt = (int)gridDim.x - 1 - (int)blockIdx.x;   // heavy tiles first
    const int bh = blockIdx.y;
    const size_t base = (size_t)bh * TT * DH;
    const int jmax = 2*qt + 1;

    // Q plane (128 rows) -> smem, part of cp.async group 0
    {
        const __half* q0 = g_qf + base + (size_t)qt * 128 * DH;
        #pragma unroll
        for (int i = 0; i < 4; i++) {
            const int ch = tid + i * 256;        // 1024 chunks
            const int r = ch >> 3, c = ch & 7;
            cp16(sb + r*144 + c*16, q0 + r*DH + c*8);
        }
    }
    const __half* kh = g_kf + base;
    const __half* vh = g_vf + base;

    auto issue_kv = [&](int jc, int st) {
        const uint32_t d0 = sb + QPL2 + st*FL_STAGE;
        const size_t g0 = (size_t)jc * 64 * DH;
        #pragma unroll
        for (int i = 0; i < 2; i++) {
            const int ch = tid + i * 256;        // 512 chunks per plane
            const int r = ch >> 3, c = ch & 7;
            const uint32_t so = r*144 + c*16;
            const size_t go = g0 + (size_t)r*DH + c*8;
            cp16(d0 +       so, kh + go);
            cp16(d0 + QPL + so, vh + go);
        }
        asm volatile("cp.async.commit_group;" ::: "memory");
    };

    issue_kv(0, 0);   // group 0 (includes Q)
    issue_kv(1, 1);   // jmax >= 1 always

    uint32_t qf[4][4];
    float oacc[8][4];
    #pragma unroll
    for (int nt = 0; nt < 8; nt++)
        #pragma unroll
        for (int e = 0; e < 4; e++) oacc[nt][e] = 0.f;
    float m0 = -INFINITY, m1 = -INFINITY, l0 = 0.f, l1 = 0.f;

    const int rsel = lane & 15;
    const uint32_t chalf = 16 * (lane >> 4);
    const int vrow = (lane & 7) + 8 * ((lane >> 4) & 1);
    const uint32_t vcol = 16 * ((lane >> 3) & 1);
    const int wrow_max = qt*128 + wid*16 + 15;   // warp's max global q-row

    int st = 0, stn = 2;    // current compute stage, next issue stage (mod 3)
    for (int jc = 0; jc <= jmax; jc++) {
        if (jc < jmax) { asm volatile("cp.async.wait_group 1;" ::: "memory"); }
        else           { asm volatile("cp.async.wait_group 0;" ::: "memory"); }
        __syncthreads();   // all warps done with stage (jc-1)%3 -> safe to refill
        if (jc + 2 <= jmax) issue_kv(jc + 2, stn);

        if (jc == 0) {   // Q fragments once (warp wid owns rows wid*16..+15)
            #pragma unroll
            for (int ku = 0; ku < 4; ku++)
                ldm_x4(qf[ku], sb + (uint32_t)((wid << 4) + rsel)*144 + ku*32 + chalf);
        }

        // fully-masked diagonal sub-tile for this warp -> skip body
        const int dlim = wrow_max - jc*64;   // cols > dlim fully masked for warp
        if (dlim >= 0) {
            const uint32_t s0 = sb + QPL2 + st*FL_STAGE;

            // ---- S = Q @ K^T (single fp16; skip fully-masked n16 groups) ----
            float s[8][4];
            #pragma unroll
            for (int nt = 0; nt < 8; nt++)
                #pragma unroll
                for (int e = 0; e < 4; e++) s[nt][e] = 0.f;

            #pragma unroll
            for (int ng = 0; ng < 4; ng++) {
                if (16*ng <= dlim) {    // warp-uniform
                    #pragma unroll
                    for (int ku = 0; ku < 4; ku++) {
                        uint32_t kh4[4];
                        ldm_x4(kh4, s0 + (uint32_t)(ng*16 + rsel)*144 + ku*32 + chalf);
                        mma_f16(s[ng*2],   qf[ku], kh4[0], kh4[2]);
                        mma_f16(s[ng*2+1], qf[ku], kh4[1], kh4[3]);
                    }
                }
            }

            // ---- scale into exp2 domain + causal mask (last two KV tiles) ----
            #pragma unroll
            for (int nt = 0; nt < 8; nt++)
                #pragma unroll
                for (int e = 0; e < 4; e++) s[nt][e] *= SM_SCALE2;
            if (jc >= 2*qt) {
                const int r0l = qt*128 + wid*16 + (lane >> 2);
                const int cbb = jc*64 + (lane & 3) * 2;
                #pragma unroll
                for (int nt = 0; nt < 8; nt++) {
                    const int c0 = cbb + nt*8;
                    if (c0     > r0l    ) s[nt][0] = -INFINITY;
                    if (c0 + 1 > r0l    ) s[nt][1] = -INFINITY;
                    if (c0     > r0l + 8) s[nt][2] = -INFINITY;
                    if (c0 + 1 > r0l + 8) s[nt][3] = -INFINITY;
                }
            }

            // ---- online softmax in exp2 domain (rows g, g+8; row on 4 lanes) ----
            float mx0 = -INFINITY, mx1 = -INFINITY;
            #pragma unroll
            for (int nt = 0; nt < 8; nt++) {
                mx0 = fmaxf(mx0, fmaxf(s[nt][0], s[nt][1]));
                mx1 = fmaxf(mx1, fmaxf(s[nt][2], s[nt][3]));
            }
            mx0 = fmaxf(mx0, __shfl_xor_sync(0xffffffffu, mx0, 1));
            mx0 = fmaxf(mx0, __shfl_xor_sync(0xffffffffu, mx0, 2));
            mx1 = fmaxf(mx1, __shfl_xor_sync(0xffffffffu, mx1, 1));
            mx1 = fmaxf(mx1, __shfl_xor_sync(0xffffffffu, mx1, 2));
            const float mn0 = fmaxf(m0, mx0), mn1 = fmaxf(m1, mx1);
            const float a0 = exp2f(m0 - mn0), a1 = exp2f(m1 - mn1);
            float sum0 = 0.f, sum1 = 0.f;
            #pragma unroll
            for (int nt = 0; nt < 8; nt++) {
                s[nt][0] = exp2f(s[nt][0] - mn0); sum0 += s[nt][0];
                s[nt][1] = exp2f(s[nt][1] - mn0); sum0 += s[nt][1];
                s[nt][2] = exp2f(s[nt][2] - mn1); sum1 += s[nt][2];
                s[nt][3] = exp2f(s[nt][3] - mn1); sum1 += s[nt][3];
            }
            sum0 += __shfl_xor_sync(0xffffffffu, sum0, 1);
            sum0 += __shfl_xor_sync(0xffffffffu, sum0, 2);
            sum1 += __shfl_xor_sync(0xffffffffu, sum1, 1);
            sum1 += __shfl_xor_sync(0xffffffffu, sum1, 2);
            l0 = l0 * a0 + sum0;  m0 = mn0;
            l1 = l1 * a1 + sum1;  m1 = mn1;
            #pragma unroll
            for (int nt = 0; nt < 8; nt++) {
                oacc[nt][0] *= a0; oacc[nt][1] *= a0;
                oacc[nt][2] *= a1; oacc[nt][3] *= a1;
            }

            // ---- O += P @ V (skip k16 groups whose P cols are all zero) ----
            #pragma unroll
            for (int u = 0; u < 4; u++) {
                if (16*u <= dlim) {     // warp-uniform
                    uint32_t pa[4];
                    #pragma unroll
                    for (int t = 0; t < 4; t++) {
                        const int j = 2*u + (t >> 1);
                        const int e0 = (t & 1) * 2;
                        pa[t] = pack_hf(s[j][e0], s[j][e0 + 1]);
                    }
                    #pragma unroll
                    for (int dg = 0; dg < 4; dg++) {
                        uint32_t vh4[4];
                        ldm_x4_t(vh4, s0 + QPL + (uint32_t)(u*16 + vrow)*144 + dg*32 + vcol);
                        mma_f16(oacc[dg*2],   pa, vh4[0], vh4[2]);
                        mma_f16(oacc[dg*2+1], pa, vh4[1], vh4[3]);
                    }
                }
            }
        }
        st  = (st  == 2) ? 0 : st  + 1;
        stn = (stn == 2) ? 0 : stn + 1;
    }

    // ---- normalize + write y [B,T,C] as fp16 (feeds fp16 proj GEMM) ----
    const int g  = lane >> 2;
    const int t2 = (lane & 3) * 2;
    const int bb = bh >> 4, hh = bh & (NH - 1);
    const int row0 = qt*128 + (wid << 4) + g;
    const float inv0 = 1.0f / l0, inv1 = 1.0f / l1;
    uint32_t* y0 = (uint32_t*)(g_yf + ((size_t)bb*TT + row0)*CC + hh*DH);
    uint32_t* y1 = (uint32_t*)(g_yf + ((size_t)bb*TT + row0 + 8)*CC + hh*DH);
    #pragma unroll
    for (int nt = 0; nt < 8; nt++) {
        y0[(nt*8 + t2) >> 1] = pack_hf(oacc[nt][0]*inv0, oacc[nt][1]*inv0);
        y1[(nt*8 + t2) >> 1] = pack_hf(oacc[nt][2]*inv1, oacc[nt][3]*inv1);
    }
}

// ---------------------------------------------------------------------------
extern "C" void kernel_launch(void* const* d_in, const int* in_sizes, int n_in,
                              void* d_out, int out_size)
{
    (void)in_sizes; (void)n_in; (void)out_size;
    const float* x     = (const float*)d_in[0];
    const float* Wqkv  = (const float*)d_in[1];
    const float* bqkv  = (const float*)d_in[2];
    const float* Wproj = (const float*)d_in[3];
    const float* bproj = (const float*)d_in[4];
    float* out = (float*)d_out;

    static bool attr_set = false;
    if (!attr_set) {
        cudaFuncSetAttribute(flash_mma_kernel,
            cudaFuncAttributeMaxDynamicSharedMemorySize, FL_SMEM_BYTES);
        cudaFuncSetAttribute(gemm_f16_kernel<0>,
            cudaFuncAttributeMaxDynamicSharedMemorySize, GEMM_SMEM);
        cudaFuncSetAttribute(gemm_f16_kernel<1>,
            cudaFuncAttributeMaxDynamicSharedMemorySize, GEMM_SMEM);
        attr_set = true;
    }

    const int act4 = (MROWS * KDIM) / 4;

    // 0) conversions (all single fp16 planes)
    conv_x<<<act4 / 256, 256>>>(x);
    conv_w<3072><<<dim3(KDIM/32, 3072/32), dim3(32, 8)>>>(Wqkv);
    conv_w<1024><<<dim3(KDIM/32, 1024/32), dim3(32, 8)>>>(Wproj);

    // 1) QKV projection (single-term fp16) -> q,k,v fp16 [B,H,T,D]
    gemm_f16_kernel<0><<<dim3(3072/128, MROWS/128), 256, GEMM_SMEM>>>(bqkv, nullptr);

    // 2) causal flash attention (Br=128) -> g_yf fp16 [B,T,C]
    flash_mma_kernel<<<dim3(TT/128, NB*NH), 256, FL_SMEM_BYTES>>>();

    // 3) output projection (single-term fp16) -> d_out
    gemm_f16_kernel<1><<<dim3(1024/128, MROWS/128), 256, GEMM_SMEM>>>(bproj, out);
}